// round 4
// baseline (speedup 1.0000x reference)
#include <cuda_runtime.h>

#define BB 32
#define SS 2048
#define DD 1024
#define EE 16
#define KK 4
#define OO 1024
#define KD 4096
#define BS (BB*SS)

// ---------------- scratch ----------------
__device__ float g_logits[BB*EE*SS];          // [b][e][s]   4 MB
__device__ int   g_tidx[BB*EE*KK];
__device__ float g_tval[BB*EE*KK];
__device__ float g_inp[(size_t)BB*EE*KD];     // [b][e][k*D] 8 MB
__device__ float g_h1[BB*EE*OO];              // 2 MB
__device__ float g_h2[BB*EE*OO];              // 2 MB

// ---------------- helpers ----------------
union F2 { unsigned long long u; float2 f; };

__device__ __forceinline__ void ffma2(F2& acc, const F2& a, const F2& b) {
    asm("fma.rn.f32x2 %0, %1, %2, %0;" : "+l"(acc.u) : "l"(a.u), "l"(b.u));
}
__device__ __forceinline__ F2 fsplat(float v) {
    F2 r;
    asm("mov.b64 %0, {%1, %1};" : "=l"(r.u) : "r"(__float_as_uint(v)));
    return r;
}
__device__ __forceinline__ F2 fpair(float lo, float hi) {
    F2 r; r.f = make_float2(lo, hi); return r;
}
__device__ __forceinline__ unsigned smem_u32(const void* p) {
    return (unsigned)__cvta_generic_to_shared(p);
}
__device__ __forceinline__ void cp_async16(unsigned dst, const void* src) {
    asm volatile("cp.async.cg.shared.global [%0], [%1], 16;" :: "r"(dst), "l"(src) : "memory");
}
__device__ __forceinline__ void cp_commit() {
    asm volatile("cp.async.commit_group;" ::: "memory");
}
__device__ __forceinline__ void cp_wait7() {
    asm volatile("cp.async.wait_group 7;" ::: "memory");
}

// ---------------- K1: gate logits -----------------------------------------
// logits[b][e][s] = x[b,s,:] . Wg[:,e]; 512 tokens/block, 2 per thread.
__global__ __launch_bounds__(256) void k1_logits(const float* __restrict__ x,
                                                 const float* __restrict__ Wg) {
    __shared__ __align__(16) float xs[512 * 20];   // token-major, pitch 20 (40KB)
    __shared__ __align__(16) float wt[16 * 20];    // WgT chunk [e][16d]
    const int tid  = threadIdx.x;
    const int tok0 = blockIdx.x * 512;

    F2 acc[32];
#pragma unroll
    for (int i = 0; i < 32; i++) acc[i].u = 0ull;

    for (int dc = 0; dc < 64; dc++) {
        __syncthreads();
#pragma unroll
        for (int i = 0; i < 8; i++) {
            const int g   = tid + 256 * i;
            const int tok = g >> 2;
            const int c4  = (g & 3) * 4;
            const float4 v = *(const float4*)(x + (size_t)(tok0 + tok) * DD + dc * 16 + c4);
            *(float4*)(xs + tok * 20 + c4) = v;
        }
        {
            const int e  = tid & 15;
            const int dd = tid >> 4;
            wt[e * 20 + dd] = Wg[(dc * 16 + dd) * EE + e];
        }
        __syncthreads();

        const float4* a0p = (const float4*)(xs + tid * 20);
        const float4* a1p = (const float4*)(xs + (tid + 256) * 20);
#pragma unroll
        for (int q = 0; q < 4; q++) {
            const float4 av0 = a0p[q];
            const float4 av1 = a1p[q];
            const F2 a00 = fpair(av0.x, av0.y), a01 = fpair(av0.z, av0.w);
            const F2 a10 = fpair(av1.x, av1.y), a11 = fpair(av1.z, av1.w);
#pragma unroll
            for (int e = 0; e < 16; e++) {
                const float4 bv = ((const float4*)(wt + e * 20))[q];   // broadcast
                const F2 b0 = fpair(bv.x, bv.y), b1 = fpair(bv.z, bv.w);
                ffma2(acc[e * 2 + 0], a00, b0);
                ffma2(acc[e * 2 + 0], a01, b1);
                ffma2(acc[e * 2 + 1], a10, b0);
                ffma2(acc[e * 2 + 1], a11, b1);
            }
        }
    }

    const int t0 = tok0 + tid;
    const int t1 = t0 + 256;
    const int b  = t0 >> 11;
    const int s0 = t0 & (SS - 1);
    const int s1 = t1 & (SS - 1);
#pragma unroll
    for (int e = 0; e < 16; e++) {
        g_logits[((size_t)(b * EE + e)) * SS + s0] = acc[e * 2 + 0].f.x + acc[e * 2 + 0].f.y;
        g_logits[((size_t)(b * EE + e)) * SS + s1] = acc[e * 2 + 1].f.x + acc[e * 2 + 1].f.y;
    }
}

// ---------------- K2: per-(b,e) softmax stats + top-4 --------------------
// One warp per (b,e). Pass 1: per-lane register top-4 (ascending scan, strict
// > keeps lowest index on ties). Butterfly merge with tie->lowest index.
// Pass 2: sum of exp(l - max).
__global__ void k2_topk() {
    const int pair = blockIdx.x * 8 + (threadIdx.x >> 5);
    const int lane = threadIdx.x & 31;
    const float* __restrict__ L = g_logits + (size_t)pair * SS;

    float t0 = -3.402823466e38f, t1 = t0, t2 = t0, t3 = t0;
    int i0 = SS, i1 = SS, i2 = SS, i3 = SS;

#pragma unroll 8
    for (int s = lane; s < SS; s += 32) {
        const float v = L[s];
        if (v > t3) {
            if (v > t1) {
                if (v > t0) { t3=t2;i3=i2; t2=t1;i2=i1; t1=t0;i1=i0; t0=v;i0=s; }
                else        { t3=t2;i3=i2; t2=t1;i2=i1; t1=v;i1=s; }
            } else {
                if (v > t2) { t3=t2;i3=i2; t2=v;i2=s; }
                else        { t3=v;i3=s; }
            }
        }
    }

    // butterfly merge of sorted-4 lists (tie -> lower index wins)
#pragma unroll
    for (int off = 16; off; off >>= 1) {
        float ov[4]; int oi[4];
        ov[0] = __shfl_xor_sync(0xffffffffu, t0, off); oi[0] = __shfl_xor_sync(0xffffffffu, i0, off);
        ov[1] = __shfl_xor_sync(0xffffffffu, t1, off); oi[1] = __shfl_xor_sync(0xffffffffu, i1, off);
        ov[2] = __shfl_xor_sync(0xffffffffu, t2, off); oi[2] = __shfl_xor_sync(0xffffffffu, i2, off);
        ov[3] = __shfl_xor_sync(0xffffffffu, t3, off); oi[3] = __shfl_xor_sync(0xffffffffu, i3, off);
#pragma unroll
        for (int c = 0; c < 4; c++) {
            const float v = ov[c]; const int ix = oi[c];
            const bool b3 = (v > t3) || (v == t3 && ix < i3);
            if (b3) {
                const bool b1 = (v > t1) || (v == t1 && ix < i1);
                if (b1) {
                    const bool b0 = (v > t0) || (v == t0 && ix < i0);
                    if (b0) { t3=t2;i3=i2; t2=t1;i2=i1; t1=t0;i1=i0; t0=v;i0=ix; }
                    else    { t3=t2;i3=i2; t2=t1;i2=i1; t1=v;i1=ix; }
                } else {
                    const bool b2 = (v > t2) || (v == t2 && ix < i2);
                    if (b2) { t3=t2;i3=i2; t2=v;i2=ix; }
                    else    { t3=v;i3=ix; }
                }
            }
        }
    }

    const float m = t0;
    float sum = 0.f;
#pragma unroll 8
    for (int s = lane; s < SS; s += 32) sum += expf(L[s] - m);
#pragma unroll
    for (int off = 16; off; off >>= 1) sum += __shfl_xor_sync(0xffffffffu, sum, off);

    if (lane == 0) {
        const float inv = 1.0f / sum;
        g_tidx[pair * 4 + 0] = i0; g_tval[pair * 4 + 0] = expf(t0 - m) * inv;
        g_tidx[pair * 4 + 1] = i1; g_tval[pair * 4 + 1] = expf(t1 - m) * inv;
        g_tidx[pair * 4 + 2] = i2; g_tval[pair * 4 + 2] = expf(t2 - m) * inv;
        g_tidx[pair * 4 + 3] = i3; g_tval[pair * 4 + 3] = expf(t3 - m) * inv;
    }
}

// ---------------- K3: gather+scale ---------------------------------------
__global__ void k3_gather(const float* __restrict__ x) {
    const int p  = blockIdx.x;
    const int k  = p & 3;
    const int be = p >> 2;
    const int b  = p >> 6;
    const int idx = g_tidx[p];
    const float val = g_tval[p];
    const float4* src = (const float4*)(x + ((size_t)b * SS + idx) * DD);
    float4* dst = (float4*)(g_inp + (size_t)be * KD + k * DD);
    const float4 v = src[threadIdx.x];
    dst[threadIdx.x] = make_float4(v.x * val, v.y * val, v.z * val, v.w * val);
}

// ---------------- grouped GEMM -------------------------------------------
// Out[32,1024] = A[32,KDIM] x W[e][KDIM,1024]  (+bias, optional relu)
// grid (8 otiles, 16 experts), 512 thr = 16 warps: warp = (rg, ks) with
// rg = 16-row group, ks = 8-way K split; lane = 4 adjacent cols.
// W rows flow through a per-warp cp.async.cg ring (depth 8 = ~500cyc
// prefetch distance, survives chunk barriers). A staged transposed with
// conflict-free stores (lane == row) and LDS.128 broadcast reads (pad 36).
#define GEMM_SMEM_BYTES (256*36*4 + 16*8*128*4)   // 36864 + 65536 = 102400

template <int KDIM>
__global__ __launch_bounds__(512) void gemm_kernel(const float* __restrict__ A,
                                                   const float* __restrict__ W,
                                                   const float* __restrict__ bias,
                                                   float* __restrict__ Out,
                                                   int doRelu) {
    constexpr int KPS = KDIM / 8;
    extern __shared__ __align__(16) float smemf[];
    float* As    = smemf;                 // [256 kk][36]
    float* wring = smemf + 256 * 36;      // [16 warps][8 slots][128 floats]

    const int tid  = threadIdx.x;
    const int lane = tid & 31;
    const int w    = tid >> 5;
    const int rg   = w & 1;
    const int ks   = w >> 1;
    const int e    = blockIdx.y;
    const int oc   = blockIdx.x * 128 + lane * 4;
    const float* Ae = A + (size_t)e * KDIM;
    const float* Wp = W + ((size_t)e * KDIM + ks * KPS) * OO + oc;

    float* myring = wring + (w * 8) * 128 + lane * 4;
    const unsigned ring_u32 = smem_u32(myring);

    // prologue: prefetch j = 0..7
#pragma unroll
    for (int j = 0; j < 8; j++) {
        cp_async16(ring_u32 + j * 512, Wp + (size_t)j * OO);
        cp_commit();
    }

    F2 acc[32];
#pragma unroll
    for (int i = 0; i < 32; i++) acc[i].u = 0ull;

    const int row = tid & 31;             // staging: lane == row (conflict-free)
    const int kkb = (tid >> 5) * 16;

    for (int kc = 0; kc < KPS; kc += 32) {
        __syncthreads();
        // stage A: 256 kk-rows (8 slices x 32 j) x 32 M-rows, transposed
#pragma unroll
        for (int c4 = 0; c4 < 16; c4 += 4) {
            const int kk    = kkb + c4;
            const int slice = kk >> 5;
            const int jj    = kk & 31;
            const float4 v = *(const float4*)(Ae + (size_t)row * (EE * KDIM)
                                              + slice * KPS + kc + jj);
            As[(kk + 0) * 36 + row] = v.x;
            As[(kk + 1) * 36 + row] = v.y;
            As[(kk + 2) * 36 + row] = v.z;
            As[(kk + 3) * 36 + row] = v.w;
        }
        __syncthreads();

#pragma unroll 4
        for (int j = 0; j < 32; j++) {
            const int jabs = kc + j;
            cp_wait7();
            const float4 q = *(const float4*)(myring + (jabs & 7) * 128);

            const float* ab = As + (ks * 32 + j) * 36 + rg * 16;
            const float4 A0 = *(const float4*)(ab);
            const float4 A1 = *(const float4*)(ab + 4);
            const float4 A2 = *(const float4*)(ab + 8);
            const float4 A3 = *(const float4*)(ab + 12);

            // prefetch j+8 (empty commit keeps group accounting uniform)
            if (jabs + 8 < KPS)
                cp_async16(ring_u32 + ((jabs + 8) & 7) * 512, Wp + (size_t)(jabs + 8) * OO);
            cp_commit();

            const F2 b0 = fsplat(q.x), b1 = fsplat(q.y),
                     b2 = fsplat(q.z), b3 = fsplat(q.w);
            F2 a[8];
            a[0] = fpair(A0.x, A0.y); a[1] = fpair(A0.z, A0.w);
            a[2] = fpair(A1.x, A1.y); a[3] = fpair(A1.z, A1.w);
            a[4] = fpair(A2.x, A2.y); a[5] = fpair(A2.z, A2.w);
            a[6] = fpair(A3.x, A3.y); a[7] = fpair(A3.z, A3.w);
#pragma unroll
            for (int rp = 0; rp < 8; rp++) {
                ffma2(acc[rp * 4 + 0], a[rp], b0);
                ffma2(acc[rp * 4 + 1], a[rp], b1);
                ffma2(acc[rp * 4 + 2], a[rp], b2);
                ffma2(acc[rp * 4 + 3], a[rp], b3);
            }
        }
    }

    // epilogue: reduce 8 K-slices via smem, bias (+relu), store
    F2* buf = (F2*)As;
#pragma unroll
    for (int rp = 0; rp < 8; rp++) {
        __syncthreads();
#pragma unroll
        for (int c = 0; c < 4; c++)
            buf[((ks * 2 + rg) * 32 + lane) * 4 + c] = acc[rp * 4 + c];
        __syncthreads();
        if (tid < 256) {
            const int rrg = tid >> 7;
            const int col = tid & 127;
            const int li  = col >> 2;
            const int ci  = col & 3;
            float sx = 0.f, sy = 0.f;
#pragma unroll
            for (int kss = 0; kss < 8; kss++) {
                const F2 v = buf[((kss * 2 + rrg) * 32 + li) * 4 + ci];
                sx += v.f.x; sy += v.f.y;
            }
            const int occol = blockIdx.x * 128 + col;
            const float bv = bias[e * OO + occol];
            sx += bv; sy += bv;
            if (doRelu) { sx = fmaxf(sx, 0.f); sy = fmaxf(sy, 0.f); }
            const int r0 = rrg * 16 + 2 * rp;
            Out[((size_t)r0 * EE + e) * OO + occol] = sx;
            Out[((size_t)(r0 + 1) * EE + e) * OO + occol] = sy;
        }
    }
}

// ---------------- launch ----------------
extern "C" void kernel_launch(void* const* d_in, const int* in_sizes, int n_in,
                              void* d_out, int out_size) {
    const float* x  = (const float*)d_in[0];
    const float* Wg = (const float*)d_in[1];
    // d_in[2] = bg: constant over the softmax (token) axis -> cancels exactly.
    const float* W1 = (const float*)d_in[3];
    const float* b1 = (const float*)d_in[4];
    const float* W2 = (const float*)d_in[5];
    const float* b2 = (const float*)d_in[6];
    const float* W3 = (const float*)d_in[7];
    const float* b3 = (const float*)d_in[8];
    float* out = (float*)d_out;

    void *pInp = nullptr, *pH1 = nullptr, *pH2 = nullptr;
    cudaGetSymbolAddress(&pInp, g_inp);
    cudaGetSymbolAddress(&pH1,  g_h1);
    cudaGetSymbolAddress(&pH2,  g_h2);

    cudaFuncSetAttribute(gemm_kernel<KD>, cudaFuncAttributeMaxDynamicSharedMemorySize, GEMM_SMEM_BYTES);
    cudaFuncSetAttribute(gemm_kernel<OO>, cudaFuncAttributeMaxDynamicSharedMemorySize, GEMM_SMEM_BYTES);

    k1_logits<<<BS / 512, 256>>>(x, Wg);
    k2_topk<<<(BB * EE) / 8, 256>>>();
    k3_gather<<<BB * EE * KK, 256>>>(x);
    gemm_kernel<KD><<<dim3(8, EE), 512, GEMM_SMEM_BYTES>>>((const float*)pInp, W1, b1, (float*)pH1, 1);
    gemm_kernel<OO><<<dim3(8, EE), 512, GEMM_SMEM_BYTES>>>((const float*)pH1,  W2, b2, (float*)pH2, 1);
    gemm_kernel<OO><<<dim3(8, EE), 512, GEMM_SMEM_BYTES>>>((const float*)pH2,  W3, b3, out, 0);
}

// round 5
// speedup vs baseline: 1.0140x; 1.0140x over previous
#include <cuda_runtime.h>

#define BB 32
#define SS 2048
#define DD 1024
#define EE 16
#define KK 4
#define OO 1024
#define KD 4096
#define BS (BB*SS)

// ---------------- scratch ----------------
__device__ float g_logits[BB*EE*SS];          // [b][e][s]   4 MB
__device__ float g_inp[(size_t)BB*EE*KD];     // [b][e][k*D] 8 MB
__device__ float g_h1[BB*EE*OO];              // 2 MB
__device__ float g_h2[BB*EE*OO];              // 2 MB

// ---------------- helpers ----------------
union F2 { unsigned long long u; float2 f; };

__device__ __forceinline__ void ffma2(F2& acc, const F2& a, const F2& b) {
    asm("fma.rn.f32x2 %0, %1, %2, %0;" : "+l"(acc.u) : "l"(a.u), "l"(b.u));
}
__device__ __forceinline__ F2 fsplat(float v) {
    F2 r;
    asm("mov.b64 %0, {%1, %1};" : "=l"(r.u) : "r"(__float_as_uint(v)));
    return r;
}
__device__ __forceinline__ F2 fpair(float lo, float hi) {
    F2 r; r.f = make_float2(lo, hi); return r;
}
__device__ __forceinline__ unsigned smem_u32(const void* p) {
    return (unsigned)__cvta_generic_to_shared(p);
}
__device__ __forceinline__ void cp_async16(unsigned dst, const void* src) {
    asm volatile("cp.async.cg.shared.global [%0], [%1], 16;" :: "r"(dst), "l"(src) : "memory");
}
__device__ __forceinline__ void cp_commit() {
    asm volatile("cp.async.commit_group;" ::: "memory");
}
__device__ __forceinline__ void cp_wait1() {
    asm volatile("cp.async.wait_group 1;" ::: "memory");
}

// ---------------- K1: gate logits -----------------------------------------
// logits[b][e][s] = x[b,s,:] . Wg[:,e]
// 256 thr, 512 tokens/block (t = tid, tid+256), grid 128.
// x chunks stream through a depth-3 cp.async ring (1 barrier per chunk).
// WgT preloaded ONCE into smem (pitch 1034 -> conflict-free + 8B aligned);
// all operand reads are direct LDS.64 -> F2 (no packs, no shuffles).
#define K1_XS_PITCH 20
#define K1_XS_BUF   (512 * K1_XS_PITCH)            // floats per ring slot
#define K1_WT_PITCH 1034
#define K1_SMEM_BYTES ((3 * K1_XS_BUF + EE * K1_WT_PITCH) * 4)   // 189,056

__global__ __launch_bounds__(256) void k1_logits(const float* __restrict__ x,
                                                 const float* __restrict__ Wg) {
    extern __shared__ __align__(16) float sm[];
    float* xs = sm;                        // [3][512][20]
    float* wt = sm + 3 * K1_XS_BUF;        // [16][1034]
    const int tid  = threadIdx.x;
    const int tok0 = blockIdx.x * 512;

    // preload all of WgT (16,384 coalesced LDG.32 -> conflict-free STS)
#pragma unroll
    for (int i = 0; i < 64; i++) {
        const int g = tid + 256 * i;       // g = d*16 + e
        wt[(g & 15) * K1_WT_PITCH + (g >> 4)] = Wg[g];
    }

    // issue x chunk c into ring slot c%3
    auto issueChunk = [&](int c) {
        const unsigned base = smem_u32(xs + (c % 3) * K1_XS_BUF);
#pragma unroll
        for (int i = 0; i < 8; i++) {
            const int idx = tid + 256 * i;           // 0..2047
            const int tok = idx >> 2;
            const int c4  = (idx & 3) * 4;
            cp_async16(base + (tok * K1_XS_PITCH + c4) * 4,
                       x + (size_t)(tok0 + tok) * DD + c * 16 + c4);
        }
        cp_commit();
    };

    issueChunk(0);
    issueChunk(1);

    F2 acc[32];
#pragma unroll
    for (int i = 0; i < 32; i++) acc[i].u = 0ull;

    for (int dc = 0; dc < 64; dc++) {
        cp_wait1();                       // chunk dc resident
        __syncthreads();                  // ..for every warp; also fences wt once
        if (dc + 2 < 64) issueChunk(dc + 2); else cp_commit();

        const float* a0p = xs + (dc % 3) * K1_XS_BUF + tid * K1_XS_PITCH;
        const float* a1p = a0p + 256 * K1_XS_PITCH;
        const float* wb  = wt + dc * 16;
#pragma unroll
        for (int q = 0; q < 4; q++) {
            const F2 a00 = *(const F2*)(a0p + q * 4);
            const F2 a01 = *(const F2*)(a0p + q * 4 + 2);
            const F2 a10 = *(const F2*)(a1p + q * 4);
            const F2 a11 = *(const F2*)(a1p + q * 4 + 2);
#pragma unroll
            for (int e = 0; e < 16; e++) {
                const F2 b0 = *(const F2*)(wb + e * K1_WT_PITCH + q * 4);
                const F2 b1 = *(const F2*)(wb + e * K1_WT_PITCH + q * 4 + 2);
                ffma2(acc[e * 2 + 0], a00, b0);
                ffma2(acc[e * 2 + 0], a01, b1);
                ffma2(acc[e * 2 + 1], a10, b0);
                ffma2(acc[e * 2 + 1], a11, b1);
            }
        }
    }

    const int t0 = tok0 + tid;
    const int t1 = t0 + 256;
    const int b  = t0 >> 11;
    const int s0 = t0 & (SS - 1);
    const int s1 = t1 & (SS - 1);
#pragma unroll
    for (int e = 0; e < 16; e++) {
        g_logits[((size_t)(b * EE + e)) * SS + s0] = acc[e * 2 + 0].f.x + acc[e * 2 + 0].f.y;
        g_logits[((size_t)(b * EE + e)) * SS + s1] = acc[e * 2 + 1].f.x + acc[e * 2 + 1].f.y;
    }
}

// ---------------- K23: softmax stats + top-4 + gather (fused) ------------
// One warp per (b,e). Register top-4 + butterfly merge (tie -> lowest idx,
// states converge on all lanes), then the same warp gathers+scales the 4
// selected token rows straight into g_inp.
__global__ void k23_topk_gather(const float* __restrict__ x) {
    const int pair = blockIdx.x * 8 + (threadIdx.x >> 5);   // b*16+e
    const int lane = threadIdx.x & 31;
    const float* __restrict__ L = g_logits + (size_t)pair * SS;

    float t0 = -3.402823466e38f, t1 = t0, t2 = t0, t3 = t0;
    int i0 = SS, i1 = SS, i2 = SS, i3 = SS;

#pragma unroll 8
    for (int s = lane; s < SS; s += 32) {
        const float v = L[s];
        if (v > t3) {
            if (v > t1) {
                if (v > t0) { t3=t2;i3=i2; t2=t1;i2=i1; t1=t0;i1=i0; t0=v;i0=s; }
                else        { t3=t2;i3=i2; t2=t1;i2=i1; t1=v;i1=s; }
            } else {
                if (v > t2) { t3=t2;i3=i2; t2=v;i2=s; }
                else        { t3=v;i3=s; }
            }
        }
    }

#pragma unroll
    for (int off = 16; off; off >>= 1) {
        float ov[4]; int oi[4];
        ov[0] = __shfl_xor_sync(0xffffffffu, t0, off); oi[0] = __shfl_xor_sync(0xffffffffu, i0, off);
        ov[1] = __shfl_xor_sync(0xffffffffu, t1, off); oi[1] = __shfl_xor_sync(0xffffffffu, i1, off);
        ov[2] = __shfl_xor_sync(0xffffffffu, t2, off); oi[2] = __shfl_xor_sync(0xffffffffu, i2, off);
        ov[3] = __shfl_xor_sync(0xffffffffu, t3, off); oi[3] = __shfl_xor_sync(0xffffffffu, i3, off);
#pragma unroll
        for (int c = 0; c < 4; c++) {
            const float v = ov[c]; const int ix = oi[c];
            const bool w3 = (v > t3) || (v == t3 && ix < i3);
            if (w3) {
                const bool w1 = (v > t1) || (v == t1 && ix < i1);
                if (w1) {
                    const bool w0 = (v > t0) || (v == t0 && ix < i0);
                    if (w0) { t3=t2;i3=i2; t2=t1;i2=i1; t1=t0;i1=i0; t0=v;i0=ix; }
                    else    { t3=t2;i3=i2; t2=t1;i2=i1; t1=v;i1=ix; }
                } else {
                    const bool w2 = (v > t2) || (v == t2 && ix < i2);
                    if (w2) { t3=t2;i3=i2; t2=v;i2=ix; }
                    else    { t3=v;i3=ix; }
                }
            }
        }
    }

    const float m = t0;
    float sum = 0.f;
#pragma unroll 8
    for (int s = lane; s < SS; s += 32) sum += expf(L[s] - m);
#pragma unroll
    for (int off = 16; off; off >>= 1) sum += __shfl_xor_sync(0xffffffffu, sum, off);

    const float inv = 1.0f / sum;                  // identical on all lanes
    const float vals[4] = { expf(t0 - m) * inv, expf(t1 - m) * inv,
                            expf(t2 - m) * inv, expf(t3 - m) * inv };
    const int   idxs[4] = { i0, i1, i2, i3 };

    const int b = pair >> 4;
    float4* dstb = (float4*)(g_inp + (size_t)pair * KD);
#pragma unroll
    for (int k = 0; k < 4; k++) {
        const float4* src = (const float4*)(x + ((size_t)b * SS + idxs[k]) * DD);
        const float val = vals[k];
#pragma unroll
        for (int it = 0; it < 8; it++) {
            const float4 v = src[lane + 32 * it];
            dstb[k * 256 + lane + 32 * it] =
                make_float4(v.x * val, v.y * val, v.z * val, v.w * val);
        }
    }
}

// ---------------- grouped GEMM -------------------------------------------
// Out[32,1024] = A[32,KDIM] x W[e][KDIM,1024]  (+bias, optional relu)
// grid (8 otiles, 16 experts), 512 thr = 16 warps: warp = (rg, ks),
// lane = 4 adjacent cols. A streams GMEM->smem via cp.async depth-3 ring
// (row-major, 1 barrier per chunk); W double-buffered in registers.
// Inner j: 16 broadcast LDS.32 + 8 packs + 4 splats + 32 FFMA2.
#define AS_PITCH 264
#define AS_BUF   (32 * AS_PITCH)                   // floats per ring slot
#define GEMM_SMEM_BYTES (3 * AS_BUF * 4)           // 101,376

template <int KDIM>
__global__ __launch_bounds__(512) void gemm_kernel(const float* __restrict__ A,
                                                   const float* __restrict__ W,
                                                   const float* __restrict__ bias,
                                                   float* __restrict__ Out,
                                                   int doRelu) {
    constexpr int KPS    = KDIM / 8;
    constexpr int CHUNKS = KPS / 32;
    extern __shared__ __align__(16) float sm[];

    const int tid  = threadIdx.x;
    const int lane = tid & 31;
    const int w    = tid >> 5;
    const int rg   = w & 1;
    const int ks   = w >> 1;
    const int e    = blockIdx.y;
    const int oc   = blockIdx.x * 128 + lane * 4;
    const float* Ae = A + (size_t)e * KDIM;
    const float* Wp = W + ((size_t)e * KDIM + ks * KPS) * OO + oc;

    // chunk c: for all 32 rows, 8 slices, the 32 k's [c*32, c*32+32)
    auto issueChunk = [&](int c) {
        const unsigned base = smem_u32(sm + (c % 3) * AS_BUF);
#pragma unroll
        for (int i = 0; i < 4; i++) {
            const int idx   = tid + 512 * i;        // 0..2047
            const int piece = idx & 7;
            const int pr    = idx >> 3;
            const int row   = pr & 31;
            const int slice = pr >> 5;
            cp_async16(base + (row * AS_PITCH + slice * 32 + piece * 4) * 4,
                       Ae + (size_t)row * (EE * KDIM) + slice * KPS + c * 32 + piece * 4);
        }
        cp_commit();
    };

    issueChunk(0);
    issueChunk(1);

    float4 wbufA[4], wbufB[4];
#pragma unroll
    for (int t = 0; t < 4; t++) wbufA[t] = *(const float4*)(Wp + (size_t)t * OO);

    F2 acc[32];
#pragma unroll
    for (int i = 0; i < 32; i++) acc[i].u = 0ull;

    for (int c = 0; c < CHUNKS; c++) {
        cp_wait1();                                 // chunk c resident
        __syncthreads();
        if (c + 2 < CHUNKS) issueChunk(c + 2); else cp_commit();

        const float* Ab = sm + (c % 3) * AS_BUF + (rg * 16) * AS_PITCH + ks * 32;
#pragma unroll
        for (int jg = 0; jg < 8; jg++) {
            const bool useA = (jg & 1) == 0;        // c*8 even -> parity = jg&1
            const int gidx = c * 8 + jg;
            if (gidx + 1 < KPS / 4) {
                const float* p = Wp + (size_t)((gidx + 1) * 4) * OO;
#pragma unroll
                for (int t = 0; t < 4; t++) {
                    const float4 v = *(const float4*)(p + (size_t)t * OO);
                    if (useA) wbufB[t] = v; else wbufA[t] = v;
                }
            }
#pragma unroll
            for (int jj = 0; jj < 4; jj++) {
                const float4 q = useA ? wbufA[jj] : wbufB[jj];
                const int j = jg * 4 + jj;
                const F2 b0 = fsplat(q.x), b1 = fsplat(q.y),
                         b2 = fsplat(q.z), b3 = fsplat(q.w);
#pragma unroll
                for (int rp = 0; rp < 8; rp++) {
                    const float* rb = Ab + rp * (2 * AS_PITCH) + j;
                    const F2 a = fpair(rb[0], rb[AS_PITCH]);
                    ffma2(acc[rp * 4 + 0], a, b0);
                    ffma2(acc[rp * 4 + 1], a, b1);
                    ffma2(acc[rp * 4 + 2], a, b2);
                    ffma2(acc[rp * 4 + 3], a, b3);
                }
            }
        }
    }

    // epilogue: reduce 8 K-slices via smem, bias (+relu), store
    F2* buf = (F2*)sm;
#pragma unroll
    for (int rp = 0; rp < 8; rp++) {
        __syncthreads();
#pragma unroll
        for (int c = 0; c < 4; c++)
            buf[((ks * 2 + rg) * 32 + lane) * 4 + c] = acc[rp * 4 + c];
        __syncthreads();
        if (tid < 256) {
            const int rrg = tid >> 7;
            const int col = tid & 127;
            const int li  = col >> 2;
            const int ci  = col & 3;
            float sx = 0.f, sy = 0.f;
#pragma unroll
            for (int kss = 0; kss < 8; kss++) {
                const F2 v = buf[((kss * 2 + rrg) * 32 + li) * 4 + ci];
                sx += v.f.x; sy += v.f.y;
            }
            const int occol = blockIdx.x * 128 + col;
            const float bv = bias[e * OO + occol];
            sx += bv; sy += bv;
            if (doRelu) { sx = fmaxf(sx, 0.f); sy = fmaxf(sy, 0.f); }
            const int r0 = rrg * 16 + 2 * rp;
            Out[((size_t)r0 * EE + e) * OO + occol] = sx;
            Out[((size_t)(r0 + 1) * EE + e) * OO + occol] = sy;
        }
    }
}

// ---------------- launch ----------------
extern "C" void kernel_launch(void* const* d_in, const int* in_sizes, int n_in,
                              void* d_out, int out_size) {
    const float* x  = (const float*)d_in[0];
    const float* Wg = (const float*)d_in[1];
    // d_in[2] = bg: constant over the softmax (token) axis -> cancels exactly.
    const float* W1 = (const float*)d_in[3];
    const float* b1 = (const float*)d_in[4];
    const float* W2 = (const float*)d_in[5];
    const float* b2 = (const float*)d_in[6];
    const float* W3 = (const float*)d_in[7];
    const float* b3 = (const float*)d_in[8];
    float* out = (float*)d_out;

    void *pInp = nullptr, *pH1 = nullptr, *pH2 = nullptr;
    cudaGetSymbolAddress(&pInp, g_inp);
    cudaGetSymbolAddress(&pH1,  g_h1);
    cudaGetSymbolAddress(&pH2,  g_h2);

    cudaFuncSetAttribute(k1_logits, cudaFuncAttributeMaxDynamicSharedMemorySize, K1_SMEM_BYTES);
    cudaFuncSetAttribute(gemm_kernel<KD>, cudaFuncAttributeMaxDynamicSharedMemorySize, GEMM_SMEM_BYTES);
    cudaFuncSetAttribute(gemm_kernel<OO>, cudaFuncAttributeMaxDynamicSharedMemorySize, GEMM_SMEM_BYTES);

    k1_logits<<<BS / 512, 256, K1_SMEM_BYTES>>>(x, Wg);
    k23_topk_gather<<<(BB * EE) / 8, 256>>>(x);
    gemm_kernel<KD><<<dim3(8, EE), 512, GEMM_SMEM_BYTES>>>((const float*)pInp, W1, b1, (float*)pH1, 1);
    gemm_kernel<OO><<<dim3(8, EE), 512, GEMM_SMEM_BYTES>>>((const float*)pH1,  W2, b2, (float*)pH2, 1);
    gemm_kernel<OO><<<dim3(8, EE), 512, GEMM_SMEM_BYTES>>>((const float*)pH2,  W3, b3, out, 0);
}

// round 6
// speedup vs baseline: 1.2117x; 1.1950x over previous
#include <cuda_runtime.h>

#define BB 32
#define SS 2048
#define DD 1024
#define EE 16
#define KK 4
#define OO 1024
#define KD 4096
#define BS (BB*SS)

// ---------------- scratch ----------------
__device__ float g_logits[BB*EE*SS];            // [b][e][s]   4 MB
__device__ int   g_tidx[BB*EE*KK];
__device__ float g_tval[BB*EE*KK];
__device__ float g_inpT[(size_t)EE*KD*BB];      // [e][kk][m=b] 8 MB
__device__ float g_h1 [BB*EE*OO];               // [m][e][o]   2 MB
__device__ float g_h1T[EE*OO*BB];               // [e][o][m]   2 MB
__device__ float g_h2 [BB*EE*OO];
__device__ float g_h2T[EE*OO*BB];

// ---------------- helpers ----------------
union F2 { unsigned long long u; float2 f; };

__device__ __forceinline__ void ffma2(F2& acc, const F2& a, const F2& b) {
    asm("fma.rn.f32x2 %0, %1, %2, %0;" : "+l"(acc.u) : "l"(a.u), "l"(b.u));
}
__device__ __forceinline__ F2 fsplat(float v) {
    F2 r;
    asm("mov.b64 %0, {%1, %1};" : "=l"(r.u) : "r"(__float_as_uint(v)));
    return r;
}
__device__ __forceinline__ unsigned smem_u32(const void* p) {
    return (unsigned)__cvta_generic_to_shared(p);
}
__device__ __forceinline__ void cp_async16(unsigned dst, const void* src) {
    asm volatile("cp.async.cg.shared.global [%0], [%1], 16;" :: "r"(dst), "l"(src) : "memory");
}
__device__ __forceinline__ void cp_commit() {
    asm volatile("cp.async.commit_group;" ::: "memory");
}
__device__ __forceinline__ void cp_wait1() {
    asm volatile("cp.async.wait_group 1;" ::: "memory");
}

// ---------------- K1: gate logits -----------------------------------------
// logits[b][e][s] = x[b,s,:] . Wg[:,e]; 512 thr, 1 token/thread, grid 128.
// x chunks stream through a depth-3 cp.async ring (1 barrier/chunk);
// WgT preloaded once (pitch 1034, conflict-free); all reads LDS.64 -> F2.
#define K1_XS_PITCH 20
#define K1_XS_BUF   (512 * K1_XS_PITCH)
#define K1_WT_PITCH 1034
#define K1_SMEM_BYTES ((3 * K1_XS_BUF + EE * K1_WT_PITCH) * 4)   // 189,056

__global__ __launch_bounds__(512) void k1_logits(const float* __restrict__ x,
                                                 const float* __restrict__ Wg) {
    extern __shared__ __align__(16) float sm[];
    float* xs = sm;                        // [3][512][20]
    float* wt = sm + 3 * K1_XS_BUF;        // [16][1034]
    const int tid  = threadIdx.x;
    const int tok0 = blockIdx.x * 512;

#pragma unroll
    for (int i = 0; i < 32; i++) {
        const int g = tid + 512 * i;       // g = d*16 + e
        wt[(g & 15) * K1_WT_PITCH + (g >> 4)] = Wg[g];
    }

    auto issueChunk = [&](int c) {
        const unsigned base = smem_u32(xs + (c % 3) * K1_XS_BUF);
#pragma unroll
        for (int i = 0; i < 4; i++) {
            const int idx = tid + 512 * i;           // 0..2047
            const int tok = idx >> 2;
            const int c4  = (idx & 3) * 4;
            cp_async16(base + (tok * K1_XS_PITCH + c4) * 4,
                       x + (size_t)(tok0 + tok) * DD + c * 16 + c4);
        }
        cp_commit();
    };

    issueChunk(0);
    issueChunk(1);

    F2 acc[16];
#pragma unroll
    for (int i = 0; i < 16; i++) acc[i].u = 0ull;

    for (int dc = 0; dc < 64; dc++) {
        cp_wait1();
        __syncthreads();
        if (dc + 2 < 64) issueChunk(dc + 2); else cp_commit();

        const float* ap = xs + (dc % 3) * K1_XS_BUF + tid * K1_XS_PITCH;
        const float* wb = wt + dc * 16;
#pragma unroll
        for (int q = 0; q < 4; q++) {
            const F2 a0 = *(const F2*)(ap + q * 4);
            const F2 a1 = *(const F2*)(ap + q * 4 + 2);
#pragma unroll
            for (int e = 0; e < 16; e++) {
                const F2 b0 = *(const F2*)(wb + e * K1_WT_PITCH + q * 4);
                const F2 b1 = *(const F2*)(wb + e * K1_WT_PITCH + q * 4 + 2);
                ffma2(acc[e], a0, b0);
                ffma2(acc[e], a1, b1);
            }
        }
    }

    const int t0 = tok0 + tid;
    const int b  = t0 >> 11;
    const int s0 = t0 & (SS - 1);
#pragma unroll
    for (int e = 0; e < 16; e++)
        g_logits[((size_t)(b * EE + e)) * SS + s0] = acc[e].f.x + acc[e].f.y;
}

// ---------------- K2: softmax stats + top-4 ------------------------------
// One warp per (b,e): register top-4 + butterfly merge (tie -> lowest idx).
__global__ void k2_topk() {
    const int pair = blockIdx.x * 8 + (threadIdx.x >> 5);   // b*16+e
    const int lane = threadIdx.x & 31;
    const float* __restrict__ L = g_logits + (size_t)pair * SS;

    float t0 = -3.402823466e38f, t1 = t0, t2 = t0, t3 = t0;
    int i0 = SS, i1 = SS, i2 = SS, i3 = SS;

#pragma unroll 8
    for (int s = lane; s < SS; s += 32) {
        const float v = L[s];
        if (v > t3) {
            if (v > t1) {
                if (v > t0) { t3=t2;i3=i2; t2=t1;i2=i1; t1=t0;i1=i0; t0=v;i0=s; }
                else        { t3=t2;i3=i2; t2=t1;i2=i1; t1=v;i1=s; }
            } else {
                if (v > t2) { t3=t2;i3=i2; t2=v;i2=s; }
                else        { t3=v;i3=s; }
            }
        }
    }

#pragma unroll
    for (int off = 16; off; off >>= 1) {
        float ov[4]; int oi[4];
        ov[0] = __shfl_xor_sync(0xffffffffu, t0, off); oi[0] = __shfl_xor_sync(0xffffffffu, i0, off);
        ov[1] = __shfl_xor_sync(0xffffffffu, t1, off); oi[1] = __shfl_xor_sync(0xffffffffu, i1, off);
        ov[2] = __shfl_xor_sync(0xffffffffu, t2, off); oi[2] = __shfl_xor_sync(0xffffffffu, i2, off);
        ov[3] = __shfl_xor_sync(0xffffffffu, t3, off); oi[3] = __shfl_xor_sync(0xffffffffu, i3, off);
#pragma unroll
        for (int c = 0; c < 4; c++) {
            const float v = ov[c]; const int ix = oi[c];
            const bool w3 = (v > t3) || (v == t3 && ix < i3);
            if (w3) {
                const bool w1 = (v > t1) || (v == t1 && ix < i1);
                if (w1) {
                    const bool w0 = (v > t0) || (v == t0 && ix < i0);
                    if (w0) { t3=t2;i3=i2; t2=t1;i2=i1; t1=t0;i1=i0; t0=v;i0=ix; }
                    else    { t3=t2;i3=i2; t2=t1;i2=i1; t1=v;i1=ix; }
                } else {
                    const bool w2 = (v > t2) || (v == t2 && ix < i2);
                    if (w2) { t3=t2;i3=i2; t2=v;i2=ix; }
                    else    { t3=v;i3=ix; }
                }
            }
        }
    }

    const float m = t0;
    float sum = 0.f;
#pragma unroll 8
    for (int s = lane; s < SS; s += 32) sum += expf(L[s] - m);
#pragma unroll
    for (int off = 16; off; off >>= 1) sum += __shfl_xor_sync(0xffffffffu, sum, off);

    if (lane == 0) {
        const float inv = 1.0f / sum;
        g_tidx[pair * 4 + 0] = i0; g_tval[pair * 4 + 0] = expf(t0 - m) * inv;
        g_tidx[pair * 4 + 1] = i1; g_tval[pair * 4 + 1] = expf(t1 - m) * inv;
        g_tidx[pair * 4 + 2] = i2; g_tval[pair * 4 + 2] = expf(t2 - m) * inv;
        g_tidx[pair * 4 + 3] = i3; g_tval[pair * 4 + 3] = expf(t3 - m) * inv;
    }
}

// ---------------- K4: gather+scale+TRANSPOSE into g_inpT ------------------
// grid (dchunk=4, k=4, e=16), block 256. Tile: 32 b x 256 d through smem.
// Output layout [e][kk = k*1024+d][m = b] so the GEMM can cp.async A verbatim.
__global__ __launch_bounds__(256) void k4_gatherT(const float* __restrict__ x) {
    __shared__ float ts[32 * 257];
    const int t  = threadIdx.x;
    const int dc = blockIdx.x;
    const int kslot = blockIdx.y;
    const int e  = blockIdx.z;

    const int brow = t >> 3;
    const int d4   = (t & 7) * 4;
    const int idx  = g_tidx[((brow * EE + e)) * KK + kslot];
    const float val = g_tval[((brow * EE + e)) * KK + kslot];
    const float* src = x + ((size_t)brow * SS + idx) * DD + dc * 256;
#pragma unroll
    for (int i = 0; i < 8; i++) {
        const int d = d4 + 32 * i;
        const float4 v = *(const float4*)(src + d);
        float* dst = ts + brow * 257 + d;
        dst[0] = v.x * val; dst[1] = v.y * val; dst[2] = v.z * val; dst[3] = v.w * val;
    }
    __syncthreads();

    float* outb = g_inpT + (size_t)e * (KD * BB)
                + ((size_t)kslot * 1024 + dc * 256) * BB;
    const int bq = t & 7;
#pragma unroll
    for (int j = 0; j < 8; j++) {
        const int d = (t >> 3) + 32 * j;
        float4 v;
        v.x = ts[(bq * 4 + 0) * 257 + d];
        v.y = ts[(bq * 4 + 1) * 257 + d];
        v.z = ts[(bq * 4 + 2) * 257 + d];
        v.w = ts[(bq * 4 + 3) * 257 + d];
        *(float4*)(outb + (size_t)d * BB + bq * 4) = v;
    }
}

// ---------------- T: transpose h [m][e][o] -> hT [e][o][m] ----------------
// grid (ochunk=4, e=16), block 256. Tile 32 m x 256 o through smem.
__global__ __launch_bounds__(256) void t_transpose(const float* __restrict__ h,
                                                   float* __restrict__ hT) {
    __shared__ float ts[32 * 257];
    const int t  = threadIdx.x;
    const int oc = blockIdx.x;
    const int e  = blockIdx.y;

    const int mrow = t >> 3;
    const int o4   = (t & 7) * 4;
    const float* src = h + ((size_t)mrow * EE + e) * OO + oc * 256;
#pragma unroll
    for (int i = 0; i < 8; i++) {
        const int o = o4 + 32 * i;
        const float4 v = *(const float4*)(src + o);
        float* dst = ts + mrow * 257 + o;
        dst[0] = v.x; dst[1] = v.y; dst[2] = v.z; dst[3] = v.w;
    }
    __syncthreads();

    float* outb = hT + (size_t)e * (OO * BB) + (size_t)(oc * 256) * BB;
    const int mq = t & 7;
#pragma unroll
    for (int j = 0; j < 8; j++) {
        const int o = (t >> 3) + 32 * j;
        float4 v;
        v.x = ts[(mq * 4 + 0) * 257 + o];
        v.y = ts[(mq * 4 + 1) * 257 + o];
        v.z = ts[(mq * 4 + 2) * 257 + o];
        v.w = ts[(mq * 4 + 3) * 257 + o];
        *(float4*)(outb + (size_t)o * BB + mq * 4) = v;
    }
}

// ---------------- grouped GEMM -------------------------------------------
// Out[m=32,1024] = AT[e][KDIM][32] x W[e][KDIM,1024]  (+bias, relu?)
// grid (8 otiles, 16 experts), 512 thr = 16 warps: warp = (rg 16-row group,
// ks 8-way K-split); lane = 4 adjacent cols. A streams via cp.async depth-3
// ring VERBATIM (layout [slice][j][m], 128B rows). W in register
// double-buffer with cross-chunk parity. Inner j: 8 broadcast LDS.64 +
// 4 splats + 32 FFMA2 -> fma-pipe bound.
#define AS_SLOT (256 * 32)                       // floats per ring slot
#define GEMM_SMEM_BYTES (3 * AS_SLOT * 4)        // 98,304

template <int KDIM>
__global__ __launch_bounds__(512) void gemm_kernel(const float* __restrict__ AT,
                                                   const float* __restrict__ W,
                                                   const float* __restrict__ bias,
                                                   float* __restrict__ Out,
                                                   int doRelu) {
    constexpr int KPS    = KDIM / 8;
    constexpr int CHUNKS = KPS / 32;
    extern __shared__ __align__(16) float sm[];

    const int tid  = threadIdx.x;
    const int lane = tid & 31;
    const int w    = tid >> 5;
    const int rg   = w & 1;
    const int ks   = w >> 1;
    const int e    = blockIdx.y;
    const int oc   = blockIdx.x * 128 + lane * 4;
    const float* Ab = AT + (size_t)e * KDIM * BB;
    const float* Wp = W + ((size_t)e * KDIM + ks * KPS) * OO + oc;

    // chunk c slot layout: [slice 0..7][j 0..31][m 0..31]
    auto issueChunk = [&](int c) {
        const unsigned base = smem_u32(sm + (c % 3) * AS_SLOT);
#pragma unroll
        for (int i = 0; i < 4; i++) {
            const int f  = tid + 512 * i;          // float4 index 0..2047
            const int kk = f >> 3;                 // 0..255
            const int m4 = (f & 7) * 4;
            cp_async16(base + (kk * 32 + m4) * 4,
                       Ab + ((size_t)(kk >> 5) * KPS + c * 32 + (kk & 31)) * BB + m4);
        }
        cp_commit();
    };

    issueChunk(0);
    issueChunk(1);

    float4 wbufA[4], wbufB[4];
#pragma unroll
    for (int t = 0; t < 4; t++) wbufA[t] = *(const float4*)(Wp + (size_t)t * OO);

    F2 acc[32];
#pragma unroll
    for (int i = 0; i < 32; i++) acc[i].u = 0ull;

    for (int c = 0; c < CHUNKS; c++) {
        cp_wait1();
        __syncthreads();
        if (c + 2 < CHUNKS) issueChunk(c + 2); else cp_commit();

        const float* As = sm + (c % 3) * AS_SLOT + (ks * 32) * 32 + rg * 16;
#pragma unroll
        for (int jg = 0; jg < 8; jg++) {
            const bool useA = (jg & 1) == 0;       // parity continues across chunks
            const int gidx = c * 8 + jg;
            if (gidx + 1 < KPS / 4) {
                const float* p = Wp + (size_t)((gidx + 1) * 4) * OO;
#pragma unroll
                for (int t = 0; t < 4; t++) {
                    const float4 v = *(const float4*)(p + (size_t)t * OO);
                    if (useA) wbufB[t] = v; else wbufA[t] = v;
                }
            }
#pragma unroll
            for (int jj = 0; jj < 4; jj++) {
                const float4 q = useA ? wbufA[jj] : wbufB[jj];
                const F2* ar = (const F2*)(As + (jg * 4 + jj) * 32);
                const F2 b0 = fsplat(q.x), b1 = fsplat(q.y),
                         b2 = fsplat(q.z), b3 = fsplat(q.w);
#pragma unroll
                for (int rp = 0; rp < 8; rp++) {
                    const F2 a = ar[rp];           // broadcast LDS.64
                    ffma2(acc[rp * 4 + 0], a, b0);
                    ffma2(acc[rp * 4 + 1], a, b1);
                    ffma2(acc[rp * 4 + 2], a, b2);
                    ffma2(acc[rp * 4 + 3], a, b3);
                }
            }
        }
    }

    // epilogue: reduce 8 K-slices via smem, bias (+relu), store [m][e][o]
    F2* buf = (F2*)sm;
#pragma unroll
    for (int rp = 0; rp < 8; rp++) {
        __syncthreads();
#pragma unroll
        for (int c = 0; c < 4; c++)
            buf[((ks * 2 + rg) * 32 + lane) * 4 + c] = acc[rp * 4 + c];
        __syncthreads();
        if (tid < 256) {
            const int rrg = tid >> 7;
            const int col = tid & 127;
            const int li  = col >> 2;
            const int ci  = col & 3;
            float sx = 0.f, sy = 0.f;
#pragma unroll
            for (int kss = 0; kss < 8; kss++) {
                const F2 v = buf[((kss * 2 + rrg) * 32 + li) * 4 + ci];
                sx += v.f.x; sy += v.f.y;
            }
            const int occol = blockIdx.x * 128 + col;
            const float bv = bias[e * OO + occol];
            sx += bv; sy += bv;
            if (doRelu) { sx = fmaxf(sx, 0.f); sy = fmaxf(sy, 0.f); }
            const int r0 = rrg * 16 + 2 * rp;
            Out[((size_t)r0 * EE + e) * OO + occol] = sx;
            Out[((size_t)(r0 + 1) * EE + e) * OO + occol] = sy;
        }
    }
}

// ---------------- launch ----------------
extern "C" void kernel_launch(void* const* d_in, const int* in_sizes, int n_in,
                              void* d_out, int out_size) {
    const float* x  = (const float*)d_in[0];
    const float* Wg = (const float*)d_in[1];
    // d_in[2] = bg: constant over the softmax (token) axis -> cancels exactly.
    const float* W1 = (const float*)d_in[3];
    const float* b1 = (const float*)d_in[4];
    const float* W2 = (const float*)d_in[5];
    const float* b2 = (const float*)d_in[6];
    const float* W3 = (const float*)d_in[7];
    const float* b3 = (const float*)d_in[8];
    float* out = (float*)d_out;

    void *pInpT=nullptr, *pH1=nullptr, *pH1T=nullptr, *pH2=nullptr, *pH2T=nullptr;
    cudaGetSymbolAddress(&pInpT, g_inpT);
    cudaGetSymbolAddress(&pH1,  g_h1);
    cudaGetSymbolAddress(&pH1T, g_h1T);
    cudaGetSymbolAddress(&pH2,  g_h2);
    cudaGetSymbolAddress(&pH2T, g_h2T);

    cudaFuncSetAttribute(k1_logits, cudaFuncAttributeMaxDynamicSharedMemorySize, K1_SMEM_BYTES);
    cudaFuncSetAttribute(gemm_kernel<KD>, cudaFuncAttributeMaxDynamicSharedMemorySize, GEMM_SMEM_BYTES);
    cudaFuncSetAttribute(gemm_kernel<OO>, cudaFuncAttributeMaxDynamicSharedMemorySize, GEMM_SMEM_BYTES);

    k1_logits<<<BS / 512, 512, K1_SMEM_BYTES>>>(x, Wg);
    k2_topk<<<(BB * EE) / 8, 256>>>();
    k4_gatherT<<<dim3(4, KK, EE), 256>>>(x);
    gemm_kernel<KD><<<dim3(8, EE), 512, GEMM_SMEM_BYTES>>>((const float*)pInpT, W1, b1, (float*)pH1, 1);
    t_transpose<<<dim3(4, EE), 256>>>((const float*)pH1, (float*)pH1T);
    gemm_kernel<OO><<<dim3(8, EE), 512, GEMM_SMEM_BYTES>>>((const float*)pH1T, W2, b2, (float*)pH2, 1);
    t_transpose<<<dim3(4, EE), 256>>>((const float*)pH2, (float*)pH2T);
    gemm_kernel<OO><<<dim3(8, EE), 512, GEMM_SMEM_BYTES>>>((const float*)pH2T, W3, b3, out, 0);
}